// round 8
// baseline (speedup 1.0000x reference)
#include <cuda_runtime.h>
#include <cstdint>

#define Bn 32
#define Fn 64
#define Ln 8192
#define Pn 96
#define SR 132    // data tile row stride (floats)
#define WR 72     // padded weight row stride in smem (floats)

typedef unsigned long long ull;

// ---------------- scratch (device globals) ----------------
__device__ float g_mean[Bn * Fn];
__device__ float g_istd[Bn * Fn];
__device__ float g_stdp[Bn * Fn];
__device__ float g_KV[Bn * 512];
__device__ float g_Z[Bn * 64];
__device__ float g_M[Bn * Pn * Fn];
// pre-folded plain-float weights, layout [k(=input dim)][e(=output dim)]
__device__ float g_Wqf[4096], g_Wkf[4096], g_Wvf[4096], g_Wof[4096];
__device__ float g_dq[64], g_cq[64], g_dk[64], g_ck[64], g_dv[64], g_cv[64];

// ---------------- helpers ----------------
__device__ __forceinline__ void fma2(ull& d, ull a, ull b) {
    asm("fma.rn.f32x2 %0, %1, %2, %0;" : "+l"(d) : "l"(a), "l"(b));
}
__device__ __forceinline__ float2 upk(ull v) {
    float2 r;
    asm("mov.b64 {%0, %1}, %2;" : "=f"(r.x), "=f"(r.y) : "l"(v));
    return r;
}
__device__ __forceinline__ ull pk2(float a, float b) {
    ull r;
    asm("mov.b64 %0, {%1, %2};" : "=l"(r) : "f"(a), "f"(b));
    return r;
}
__device__ __forceinline__ ull dup(float a) { return pk2(a, a); }
__device__ __forceinline__ float phi_fn(float v) {
    return v > 0.f ? v + 1.f : __expf(v);   // elu(x)+1
}

// ---------------- prep (block 0) + zero accumulators (blocks 1..32) ----------------
__global__ void __launch_bounds__(256) k_prep(
    const float* __restrict__ lnw, const float* __restrict__ lnb,
    const float* __restrict__ Wq, const float* __restrict__ bq,
    const float* __restrict__ Wk, const float* __restrict__ bk,
    const float* __restrict__ Wv, const float* __restrict__ bv,
    const float* __restrict__ Wo)
{
    if (blockIdx.x > 0) {
        int zb = blockIdx.x - 1;                 // 0..31
        int base = zb * 6144;                    // 32*6144 = 196608 = Bn*Pn*Fn
        for (int i = threadIdx.x; i < 6144; i += 256) g_M[base + i] = 0.f;
        if (zb < 16) {
            for (int i = threadIdx.x; i < 1024; i += 256) g_KV[zb * 1024 + i] = 0.f;
        } else {
            int zz = zb - 16;
            for (int i = threadIdx.x; i < 128; i += 256) g_Z[zz * 128 + i] = 0.f;
        }
        return;
    }
    int tid = threadIdx.x;
#pragma unroll
    for (int i = 0; i < 16; i++) {
        int idx = tid + i * 256;          // idx = f*64 + e
        int f = idx >> 6, e = idx & 63;
        float lw = lnw[f];
        g_Wqf[idx] = Wq[e * 64 + f] * lw;
        g_Wkf[idx] = Wk[e * 64 + f] * lw;
        g_Wvf[idx] = Wv[e * 64 + f] * lw;
        g_Wof[idx] = Wo[e * 64 + f];      // WoT[k=e_att][fo]
    }
    if (tid < 64) {
        int e = tid;
        float dq = 0.f, cq = 0.f, dk = 0.f, ck = 0.f, dv = 0.f, cv = 0.f;
        for (int f = 0; f < 64; f++) {
            float lw = lnw[f], lb2 = lnb[f];
            float wq = Wq[e * 64 + f], wk = Wk[e * 64 + f], wv = Wv[e * 64 + f];
            dq += wq * lw;  cq = fmaf(lb2, wq, cq);
            dk += wk * lw;  ck = fmaf(lb2, wk, ck);
            dv += wv * lw;  cv = fmaf(lb2, wv, cv);
        }
        g_dq[e] = dq; g_cq[e] = cq + bq[e];
        g_dk[e] = dk; g_ck[e] = ck + bk[e];
        g_dv[e] = dv; g_cv[e] = cv + bv[e];
    }
}

// ---------------- RevIN stats per (b,f) ----------------
__global__ void __launch_bounds__(256) k_stats(const float* __restrict__ x) {
    int bf = blockIdx.x;
    const float4* p = (const float4*)(x + (size_t)bf * Ln);
    float s1 = 0.f, s2 = 0.f;
    for (int i = threadIdx.x; i < Ln / 4; i += 256) {
        float4 v = p[i];
        s1 += (v.x + v.y) + (v.z + v.w);
        s2 = fmaf(v.x, v.x, s2); s2 = fmaf(v.y, v.y, s2);
        s2 = fmaf(v.z, v.z, s2); s2 = fmaf(v.w, v.w, s2);
    }
    __shared__ float r1[256], r2[256];
    r1[threadIdx.x] = s1; r2[threadIdx.x] = s2;
    __syncthreads();
    for (int s = 128; s > 0; s >>= 1) {
        if (threadIdx.x < s) {
            r1[threadIdx.x] += r1[threadIdx.x + s];
            r2[threadIdx.x] += r2[threadIdx.x + s];
        }
        __syncthreads();
    }
    if (threadIdx.x == 0) {
        float S1 = r1[0], S2 = r2[0];
        float mean = S1 / (float)Ln;
        float var = (S2 - S1 * mean) / (float)(Ln - 1);
        var = fmaxf(var, 0.f);
        float stdp = sqrtf(var) + 1e-5f;
        g_mean[bf] = mean; g_stdp[bf] = stdp; g_istd[bf] = 1.f / stdp;
    }
}

// ---------------- kernel 2: fused K+V projections + KV,Z (512 threads) ----------------
__global__ void __launch_bounds__(512, 2) k_kv(
    const float* __restrict__ x, const float* __restrict__ gamma, const float* __restrict__ beta)
{
    extern __shared__ float sm[];
    float* xns = sm;                     // 64*SR; later phi(K)
    float* vb  = sm + 64 * SR;           // 64*SR
    float* wv  = sm + 2 * 64 * SR;       // 64*WR
    float* wk  = wv + 64 * WR;           // 64*WR
    __shared__ float mus[128], rss[128], As[64], Cs[64];
    __shared__ float dks[64], cks[64], dvs[64], cvs[64];

    int b = blockIdx.y, tid = threadIdx.x;
    int l0b = blockIdx.x * 128;

    if (tid < 64) {
        float a = gamma[tid] * g_istd[b * 64 + tid];
        As[tid] = a;
        Cs[tid] = beta[tid] - g_mean[b * 64 + tid] * a;
        dks[tid] = g_dk[tid]; cks[tid] = g_ck[tid];
        dvs[tid] = g_dv[tid]; cvs[tid] = g_cv[tid];
    }
    // stage weights, padded rows: dst = k*WR + e4 + 4*(e4>=32)
#pragma unroll
    for (int i = 0; i < 2; i++) {
        int idx = tid + i * 512;                  // 1024 float4s
        int kk = idx >> 4, e4 = (idx & 15) * 4;
        int dsto = kk * WR + e4 + ((e4 & 32) >> 3);
        *(float4*)(wv + dsto) = ((const float4*)g_Wvf)[idx];
        *(float4*)(wk + dsto) = ((const float4*)g_Wkf)[idx];
    }
    __syncthreads();
#pragma unroll
    for (int i = 0; i < 4; i++) {
        int idx = tid + i * 512;
        int f = idx >> 5, c = idx & 31;
        float4 v = *(const float4*)(x + ((size_t)(b * 64 + f)) * Ln + l0b + c * 4);
        float a = As[f], c0 = Cs[f];
        v.x = fmaf(v.x, a, c0); v.y = fmaf(v.y, a, c0);
        v.z = fmaf(v.z, a, c0); v.w = fmaf(v.w, a, c0);
        *(float4*)(xns + f * SR + c * 4) = v;
    }
    __syncthreads();
    if (tid < 128) {
        float s1 = 0.f, s2 = 0.f;
#pragma unroll
        for (int f = 0; f < 64; f++) { float t = xns[f * SR + tid]; s1 += t; s2 = fmaf(t, t, s2); }
        float mu = s1 * (1.f / 64.f);
        mus[tid] = mu;
        rss[tid] = rsqrtf(fmaf(-mu, mu, s2 * (1.f / 64.f)) + 1e-5f);
    }
    __syncthreads();

    // thread tile: 2 l x 8 e ; pairs along e (natural in weight memory)
    int lane = tid & 31, wrp = tid >> 5;
    int eg = lane >> 2, lsub = lane & 3;
    int l0 = 2 * (lsub + 4 * wrp);       // 0..126 even
    int e0 = 8 * eg;                     // 0..56
    const float* hp = xns + l0;
    const float* wvp = wv + e0 + ((e0 & 32) >> 3);
    const float* wkp = wk + e0 + ((e0 & 32) >> 3);

    ull aV[4][2], aK[4][2];
#pragma unroll
    for (int i = 0; i < 4; i++) { aV[i][0] = aV[i][1] = aK[i][0] = aK[i][1] = 0ULL; }
#pragma unroll 8
    for (int k = 0; k < 64; k++) {
        float2 hx = *(const float2*)(hp + k * SR);
        ull h0 = dup(hx.x), h1 = dup(hx.y);
        ulonglong2 wvA = *(const ulonglong2*)(wvp + k * WR);
        ulonglong2 wvB = *(const ulonglong2*)(wvp + k * WR + 4);
        ulonglong2 wkA = *(const ulonglong2*)(wkp + k * WR);
        ulonglong2 wkB = *(const ulonglong2*)(wkp + k * WR + 4);
        fma2(aV[0][0], wvA.x, h0); fma2(aV[0][1], wvA.x, h1);
        fma2(aV[1][0], wvA.y, h0); fma2(aV[1][1], wvA.y, h1);
        fma2(aV[2][0], wvB.x, h0); fma2(aV[2][1], wvB.x, h1);
        fma2(aV[3][0], wvB.y, h0); fma2(aV[3][1], wvB.y, h1);
        fma2(aK[0][0], wkA.x, h0); fma2(aK[0][1], wkA.x, h1);
        fma2(aK[1][0], wkA.y, h0); fma2(aK[1][1], wkA.y, h1);
        fma2(aK[2][0], wkB.x, h0); fma2(aK[2][1], wkB.x, h1);
        fma2(aK[3][0], wkB.y, h0); fma2(aK[3][1], wkB.y, h1);
    }

    float mu0 = mus[l0], mu1 = mus[l0 + 1];
    float rs0 = rss[l0], rs1 = rss[l0 + 1];

    // ---- V epilogue -> vb (vb not read by GEMM: no sync needed) ----
#pragma unroll
    for (int ep = 0; ep < 4; ep++) {
        int e = e0 + 2 * ep;
        float2 s0 = upk(aV[ep][0]);   // (v_e, v_{e+1}) at column l0
        float2 s1 = upk(aV[ep][1]);   // at column l0+1
        vb[e * SR + l0]           = fmaf(rs0, s0.x - mu0 * dvs[e],     cvs[e]);
        vb[(e + 1) * SR + l0]     = fmaf(rs0, s0.y - mu0 * dvs[e + 1], cvs[e + 1]);
        vb[e * SR + l0 + 1]       = fmaf(rs1, s1.x - mu1 * dvs[e],     cvs[e]);
        vb[(e + 1) * SR + l0 + 1] = fmaf(rs1, s1.y - mu1 * dvs[e + 1], cvs[e + 1]);
    }
    // ---- K epilogue: phi in regs ----
    float kf[4][4];
#pragma unroll
    for (int ep = 0; ep < 4; ep++) {
        int e = e0 + 2 * ep;
        float2 s0 = upk(aK[ep][0]);
        float2 s1 = upk(aK[ep][1]);
        kf[ep][0] = phi_fn(fmaf(rs0, s0.x - mu0 * dks[e],     cks[e]));
        kf[ep][1] = phi_fn(fmaf(rs0, s0.y - mu0 * dks[e + 1], cks[e + 1]));
        kf[ep][2] = phi_fn(fmaf(rs1, s1.x - mu1 * dks[e],     cks[e]));
        kf[ep][3] = phi_fn(fmaf(rs1, s1.y - mu1 * dks[e + 1], cks[e + 1]));
    }
    __syncthreads();   // all GEMM reads of xns done
#pragma unroll
    for (int ep = 0; ep < 4; ep++) {
        int e = e0 + 2 * ep;
        xns[e * SR + l0]           = kf[ep][0];
        xns[(e + 1) * SR + l0]     = kf[ep][1];
        xns[e * SR + l0 + 1]       = kf[ep][2];
        xns[(e + 1) * SR + l0 + 1] = kf[ep][3];
    }
    __syncthreads();

    // ---- KV accumulation: one (hh,d,e) per thread ----
    {
        int hh = tid >> 6;
        int d  = (tid >> 3) & 7;
        int e2 = tid & 7;
        const float* kr = xns + (hh * 8 + d) * SR;
        const float* vr = vb + (hh * 8 + e2) * SR;
        ull a = 0ULL;
#pragma unroll 8
        for (int j = 0; j < 128; j += 4) {
            ulonglong2 kk = *(const ulonglong2*)(kr + j);
            ulonglong2 vv = *(const ulonglong2*)(vr + j);
            fma2(a, kk.x, vv.x);
            fma2(a, kk.y, vv.y);
        }
        float2 t = upk(a);
        atomicAdd(&g_KV[(b * 8 + hh) * 64 + d * 8 + e2], t.x + t.y);
    }
    if (tid < 64) {
        const float* kr = xns + tid * SR;
        float s = 0.f;
#pragma unroll
        for (int j = 0; j < 128; j += 4) {
            float4 v = *(const float4*)(kr + j);
            s += (v.x + v.y) + (v.z + v.w);
        }
        atomicAdd(&g_Z[b * 64 + tid], s);
    }
}

// ---------------- kernel 3: Q, attention, Wo+residual, fused temporal (512 threads) ----------------
__global__ void __launch_bounds__(512, 2) k_qo(
    const float* __restrict__ x, const float* __restrict__ gamma, const float* __restrict__ beta,
    const float* __restrict__ bo, const float* __restrict__ Wlin)
{
    extern __shared__ float sm[];
    float* wq  = sm;                     // 64*WR (Wq, then WoT)
    float* xns = sm + 64 * WR;           // 64*SR
    float* qb  = sm + 64 * WR + 64 * SR; // 64*SR; later y tile (66-ull row stride)
    ull*   wy  = (ull*)qb;               // y: 64 rows x 66 ulls = 33792 B (region is 64*SR*4 = 33792 exactly)
    ull*   wlu = (ull*)sm;               // Wlin slab: 96 rows x 64 ulls = 49152 B over wq+xns (52224 B)
    __shared__ float mus[128], rss[128], As[64], Cs[64], dqs[64], cqs[64], bos[64];
    __shared__ float KVs[512], Zs[64];

    int b = blockIdx.y, tid = threadIdx.x;
    int l0b = blockIdx.x * 128;

    if (tid < 64) {
        float a = gamma[tid] * g_istd[b * 64 + tid];
        As[tid] = a;
        Cs[tid] = beta[tid] - g_mean[b * 64 + tid] * a;
        dqs[tid] = g_dq[tid]; cqs[tid] = g_cq[tid];
        bos[tid] = bo[tid];
        Zs[tid] = g_Z[b * 64 + tid];
    }
    KVs[tid] = g_KV[b * 512 + tid];
#pragma unroll
    for (int i = 0; i < 2; i++) {
        int idx = tid + i * 512;
        int kk = idx >> 4, e4 = (idx & 15) * 4;
        *(float4*)(wq + kk * WR + e4 + ((e4 & 32) >> 3)) = ((const float4*)g_Wqf)[idx];
    }
    __syncthreads();
#pragma unroll
    for (int i = 0; i < 4; i++) {
        int idx = tid + i * 512;
        int f = idx >> 5, c = idx & 31;
        float4 v = *(const float4*)(x + ((size_t)(b * 64 + f)) * Ln + l0b + c * 4);
        float a = As[f], c0 = Cs[f];
        v.x = fmaf(v.x, a, c0); v.y = fmaf(v.y, a, c0);
        v.z = fmaf(v.z, a, c0); v.w = fmaf(v.w, a, c0);
        *(float4*)(xns + f * SR + c * 4) = v;
    }
    __syncthreads();
    if (tid < 128) {
        float s1 = 0.f, s2 = 0.f;
#pragma unroll
        for (int f = 0; f < 64; f++) { float t = xns[f * SR + tid]; s1 += t; s2 = fmaf(t, t, s2); }
        float mu = s1 * (1.f / 64.f);
        mus[tid] = mu;
        rss[tid] = rsqrtf(fmaf(-mu, mu, s2 * (1.f / 64.f)) + 1e-5f);
    }
    __syncthreads();

    int lane = tid & 31, wrp = tid >> 5;
    int eg = lane >> 2, lsub = lane & 3;
    int l0 = 2 * (lsub + 4 * wrp);
    int e0 = 8 * eg;
    const float* wqp = wq + e0 + ((e0 & 32) >> 3);

    float mu0 = mus[l0], mu1 = mus[l0 + 1];
    float rs0 = rss[l0], rs1 = rss[l0 + 1];

    // ---- Q GEMM -> phi -> qb ----
    {
        const float* hp = xns + l0;
        ull a[4][2];
#pragma unroll
        for (int i = 0; i < 4; i++) { a[i][0] = a[i][1] = 0ULL; }
#pragma unroll 8
        for (int k = 0; k < 64; k++) {
            float2 hx = *(const float2*)(hp + k * SR);
            ull h0 = dup(hx.x), h1 = dup(hx.y);
            ulonglong2 wA = *(const ulonglong2*)(wqp + k * WR);
            ulonglong2 wB = *(const ulonglong2*)(wqp + k * WR + 4);
            fma2(a[0][0], wA.x, h0); fma2(a[0][1], wA.x, h1);
            fma2(a[1][0], wA.y, h0); fma2(a[1][1], wA.y, h1);
            fma2(a[2][0], wB.x, h0); fma2(a[2][1], wB.x, h1);
            fma2(a[3][0], wB.y, h0); fma2(a[3][1], wB.y, h1);
        }
#pragma unroll
        for (int ep = 0; ep < 4; ep++) {
            int e = e0 + 2 * ep;
            float2 s0 = upk(a[ep][0]);
            float2 s1 = upk(a[ep][1]);
            qb[e * SR + l0]           = phi_fn(fmaf(rs0, s0.x - mu0 * dqs[e],     cqs[e]));
            qb[(e + 1) * SR + l0]     = phi_fn(fmaf(rs0, s0.y - mu0 * dqs[e + 1], cqs[e + 1]));
            qb[e * SR + l0 + 1]       = phi_fn(fmaf(rs1, s1.x - mu1 * dqs[e],     cqs[e]));
            qb[(e + 1) * SR + l0 + 1] = phi_fn(fmaf(rs1, s1.y - mu1 * dqs[e + 1], cqs[e + 1]));
        }
    }
    __syncthreads();   // q complete; Wq reads done

    // ---- reload w <- WoT (padded); attention (2 heads/thread, own cells) ----
#pragma unroll
    for (int i = 0; i < 2; i++) {
        int idx = tid + i * 512;
        int kk = idx >> 4, e4 = (idx & 15) * 4;
        *(float4*)(wq + kk * WR + e4 + ((e4 & 32) >> 3)) = ((const float4*)g_Wof)[idx];
    }
    {
        int la = tid & 127;
        int hgrp = tid >> 7;   // 0..3
#pragma unroll
        for (int t = 0; t < 2; t++) {
            int hh = hgrp * 2 + t;
            float q[8];
#pragma unroll
            for (int d = 0; d < 8; d++) q[d] = qb[(hh * 8 + d) * SR + la];
            float nrm = 1e-6f;
#pragma unroll
            for (int d = 0; d < 8; d++) nrm = fmaf(q[d], Zs[hh * 8 + d], nrm);
            float inv = 1.f / nrm;
#pragma unroll
            for (int j = 0; j < 8; j++) {
                float s = 0.f;
#pragma unroll
                for (int d = 0; d < 8; d++) s = fmaf(q[d], KVs[hh * 64 + d * 8 + j], s);
                qb[(hh * 8 + j) * SR + la] = s * inv;
            }
        }
    }
    __syncthreads();

    // ---- Wo GEMM + bias + residual -> y values in regs ----
    float yv[4][4];
    {
        const float* hp = qb + l0;
        ull a[4][2];
#pragma unroll
        for (int i = 0; i < 4; i++) { a[i][0] = a[i][1] = 0ULL; }
#pragma unroll 8
        for (int k = 0; k < 64; k++) {
            float2 hx = *(const float2*)(hp + k * SR);
            ull h0 = dup(hx.x), h1 = dup(hx.y);
            ulonglong2 wA = *(const ulonglong2*)(wqp + k * WR);
            ulonglong2 wB = *(const ulonglong2*)(wqp + k * WR + 4);
            fma2(a[0][0], wA.x, h0); fma2(a[0][1], wA.x, h1);
            fma2(a[1][0], wA.y, h0); fma2(a[1][1], wA.y, h1);
            fma2(a[2][0], wB.x, h0); fma2(a[2][1], wB.x, h1);
            fma2(a[3][0], wB.y, h0); fma2(a[3][1], wB.y, h1);
        }
#pragma unroll
        for (int ep = 0; ep < 4; ep++) {
            int fo = e0 + 2 * ep;
            float2 r0 = *(const float2*)(xns + fo * SR + l0);
            float2 r1 = *(const float2*)(xns + (fo + 1) * SR + l0);
            float2 s0 = upk(a[ep][0]);   // (y_fo, y_fo+1) at l0
            float2 s1 = upk(a[ep][1]);   // at l0+1
            yv[ep][0] = s0.x + bos[fo]     + r0.x;
            yv[ep][1] = s0.y + bos[fo + 1] + r1.x;
            yv[ep][2] = s1.x + bos[fo]     + r0.y;
            yv[ep][3] = s1.y + bos[fo + 1] + r1.y;
        }
    }
    __syncthreads();   // all Wo GEMM qb-reads + residual xns-reads done

    // ---- store y (132-float rows over qb region) + Wlin slab over wq+xns ----
    {
        float* wyf = qb;   // float view, row stride 132
#pragma unroll
        for (int ep = 0; ep < 4; ep++) {
            int fo = e0 + 2 * ep;
            wyf[fo * 132 + l0]           = yv[ep][0];
            wyf[(fo + 1) * 132 + l0]     = yv[ep][1];
            wyf[fo * 132 + l0 + 1]       = yv[ep][2];
            wyf[(fo + 1) * 132 + l0 + 1] = yv[ep][3];
        }
    }
#pragma unroll
    for (int i = 0; i < 6; i++) {
        int idx = tid + i * 512;               // 3072 float4 = 96 rows x 32
        int p = idx >> 5, c4 = idx & 31;
        ((float4*)wlu)[(p << 5) + c4] = *(const float4*)(Wlin + (size_t)p * Ln + l0b + c4 * 4);
    }
    __syncthreads();

    // ---- temporal GEMM: M[b,p,f] += sum_l Wlin[p,l] * y[f,l] ----
    int fg = tid & 15, pg2 = tid >> 4;          // 16 f-groups x 32 p-groups
    ull acc2[3][4];
#pragma unroll
    for (int i = 0; i < 3; i++)
#pragma unroll
        for (int k = 0; k < 4; k++) acc2[i][k] = 0ULL;
#pragma unroll 4
    for (int j = 0; j < 64; j += 2) {
        ulonglong2 yvv[4], wvv[3];
#pragma unroll
        for (int k = 0; k < 4; k++) yvv[k] = *(const ulonglong2*)(wy + (fg + 16 * k) * 66 + j);
#pragma unroll
        for (int i = 0; i < 3; i++) wvv[i] = *(const ulonglong2*)(wlu + (pg2 + 32 * i) * 64 + j);
#pragma unroll
        for (int i = 0; i < 3; i++)
#pragma unroll
            for (int k = 0; k < 4; k++) {
                fma2(acc2[i][k], wvv[i].x, yvv[k].x);
                fma2(acc2[i][k], wvv[i].y, yvv[k].y);
            }
    }
#pragma unroll
    for (int i = 0; i < 3; i++)
#pragma unroll
        for (int k = 0; k < 4; k++) {
            float2 t = upk(acc2[i][k]);
            atomicAdd(&g_M[(b * 96 + pg2 + 32 * i) * 64 + fg + 16 * k], t.x + t.y);
        }
}

// ---------------- kernel 5: denorm + projector ----------------
__global__ void k_epi(const float* __restrict__ gamma, const float* __restrict__ beta,
                      const float* __restrict__ blin, const float* __restrict__ Wp,
                      const float* __restrict__ bp, float* __restrict__ out) {
    int b = blockIdx.x, p = threadIdx.x;
    float bl = blin[p];
    float s = bp[0];
#pragma unroll
    for (int f = 0; f < 64; f++) {
        float y = g_M[(b * 96 + p) * 64 + f] + bl;
        y = (y - beta[f]) / gamma[f];
        y = fmaf(y, g_stdp[b * 64 + f], g_mean[b * 64 + f]);
        s = fmaf(y, Wp[f], s);
    }
    out[b * 96 + p] = s;
}

// ---------------- launch ----------------
extern "C" void kernel_launch(void* const* d_in, const int* in_sizes, int n_in,
                              void* d_out, int out_size) {
    (void)in_sizes; (void)n_in; (void)out_size;
    const float* x     = (const float*)d_in[0];
    const float* gamma = (const float*)d_in[1];
    const float* beta  = (const float*)d_in[2];
    const float* lnw   = (const float*)d_in[3];
    const float* lnb   = (const float*)d_in[4];
    const float* Wq    = (const float*)d_in[5];
    const float* bq    = (const float*)d_in[6];
    const float* Wk    = (const float*)d_in[7];
    const float* bk    = (const float*)d_in[8];
    const float* Wv    = (const float*)d_in[9];
    const float* bv    = (const float*)d_in[10];
    const float* Wo    = (const float*)d_in[11];
    const float* bo    = (const float*)d_in[12];
    const float* Wlin  = (const float*)d_in[13];
    const float* blin  = (const float*)d_in[14];
    const float* Wp    = (const float*)d_in[15];
    const float* bp    = (const float*)d_in[16];
    float* out = (float*)d_out;

    const int SMB_KV = (2 * 64 * SR + 2 * 64 * WR) * 4;   // 67584 + 36864 = 104448 B
    const int SMB_QO = (64 * WR + 2 * 64 * SR) * 4;       // 18432 + 67584 = 86016 B
    cudaFuncSetAttribute(k_kv, cudaFuncAttributeMaxDynamicSharedMemorySize, SMB_KV);
    cudaFuncSetAttribute(k_qo, cudaFuncAttributeMaxDynamicSharedMemorySize, SMB_QO);

    k_prep<<<33, 256>>>(lnw, lnb, Wq, bq, Wk, bk, Wv, bv, Wo);
    k_stats<<<Bn * Fn, 256>>>(x);
    k_kv<<<dim3(Ln / 128, Bn), 512, SMB_KV>>>(x, gamma, beta);
    k_qo<<<dim3(Ln / 128, Bn), 512, SMB_QO>>>(x, gamma, beta, bo, Wlin);
    k_epi<<<Bn, Pn>>>(gamma, beta, blin, Wp, bp, out);
}

// round 9
// speedup vs baseline: 1.0025x; 1.0025x over previous
#include <cuda_runtime.h>
#include <cstdint>

#define Bn 32
#define Fn 64
#define Ln 8192
#define Pn 96
#define SR 132    // data tile row stride (floats)
#define WR 72     // padded weight row stride in smem (floats)

typedef unsigned long long ull;

// ---------------- scratch (device globals) ----------------
__device__ float g_mean[Bn * Fn];
__device__ float g_istd[Bn * Fn];
__device__ float g_stdp[Bn * Fn];
__device__ float g_KV[Bn * 512];
__device__ float g_Z[Bn * 64];
__device__ float g_M[Bn * Pn * Fn];
// pre-folded plain-float weights, layout [k(=input dim)][e(=output dim)]
__device__ float g_Wqf[4096], g_Wkf[4096], g_Wvf[4096], g_Wof[4096];
__device__ float g_dq[64], g_cq[64], g_dk[64], g_ck[64], g_dv[64], g_cv[64];

// ---------------- helpers ----------------
__device__ __forceinline__ void fma2(ull& d, ull a, ull b) {
    asm("fma.rn.f32x2 %0, %1, %2, %0;" : "+l"(d) : "l"(a), "l"(b));
}
__device__ __forceinline__ float2 upk(ull v) {
    float2 r;
    asm("mov.b64 {%0, %1}, %2;" : "=f"(r.x), "=f"(r.y) : "l"(v));
    return r;
}
__device__ __forceinline__ ull pk2(float a, float b) {
    ull r;
    asm("mov.b64 %0, {%1, %2};" : "=l"(r) : "f"(a), "f"(b));
    return r;
}
__device__ __forceinline__ ull dup(float a) { return pk2(a, a); }
__device__ __forceinline__ float phi_fn(float v) {
    return v > 0.f ? v + 1.f : __expf(v);   // elu(x)+1
}

// ---------------- prep (block 0) + zero accumulators (blocks 1..32) ----------------
__global__ void __launch_bounds__(256) k_prep(
    const float* __restrict__ lnw, const float* __restrict__ lnb,
    const float* __restrict__ Wq, const float* __restrict__ bq,
    const float* __restrict__ Wk, const float* __restrict__ bk,
    const float* __restrict__ Wv, const float* __restrict__ bv,
    const float* __restrict__ Wo)
{
    if (blockIdx.x > 0) {
        int zb = blockIdx.x - 1;                 // 0..31
        int base = zb * 6144;                    // 32*6144 = 196608 = Bn*Pn*Fn
        for (int i = threadIdx.x; i < 6144; i += 256) g_M[base + i] = 0.f;
        if (zb < 16) {
            for (int i = threadIdx.x; i < 1024; i += 256) g_KV[zb * 1024 + i] = 0.f;
        } else {
            int zz = zb - 16;
            for (int i = threadIdx.x; i < 128; i += 256) g_Z[zz * 128 + i] = 0.f;
        }
        return;
    }
    int tid = threadIdx.x;
#pragma unroll
    for (int i = 0; i < 16; i++) {
        int idx = tid + i * 256;          // idx = f*64 + e
        int f = idx >> 6, e = idx & 63;
        float lw = lnw[f];
        g_Wqf[idx] = Wq[e * 64 + f] * lw;
        g_Wkf[idx] = Wk[e * 64 + f] * lw;
        g_Wvf[idx] = Wv[e * 64 + f] * lw;
        g_Wof[idx] = Wo[e * 64 + f];      // WoT[k=e_att][fo]
    }
    if (tid < 64) {
        int e = tid;
        float dq = 0.f, cq = 0.f, dk = 0.f, ck = 0.f, dv = 0.f, cv = 0.f;
        for (int f = 0; f < 64; f++) {
            float lw = lnw[f], lb2 = lnb[f];
            float wq = Wq[e * 64 + f], wk = Wk[e * 64 + f], wv = Wv[e * 64 + f];
            dq += wq * lw;  cq = fmaf(lb2, wq, cq);
            dk += wk * lw;  ck = fmaf(lb2, wk, ck);
            dv += wv * lw;  cv = fmaf(lb2, wv, cv);
        }
        g_dq[e] = dq; g_cq[e] = cq + bq[e];
        g_dk[e] = dk; g_ck[e] = ck + bk[e];
        g_dv[e] = dv; g_cv[e] = cv + bv[e];
    }
}

// ---------------- RevIN stats per (b,f) ----------------
__global__ void __launch_bounds__(256) k_stats(const float* __restrict__ x) {
    int bf = blockIdx.x;
    const float4* p = (const float4*)(x + (size_t)bf * Ln);
    float s1 = 0.f, s2 = 0.f;
    for (int i = threadIdx.x; i < Ln / 4; i += 256) {
        float4 v = p[i];
        s1 += (v.x + v.y) + (v.z + v.w);
        s2 = fmaf(v.x, v.x, s2); s2 = fmaf(v.y, v.y, s2);
        s2 = fmaf(v.z, v.z, s2); s2 = fmaf(v.w, v.w, s2);
    }
    __shared__ float r1[256], r2[256];
    r1[threadIdx.x] = s1; r2[threadIdx.x] = s2;
    __syncthreads();
    for (int s = 128; s > 0; s >>= 1) {
        if (threadIdx.x < s) {
            r1[threadIdx.x] += r1[threadIdx.x + s];
            r2[threadIdx.x] += r2[threadIdx.x + s];
        }
        __syncthreads();
    }
    if (threadIdx.x == 0) {
        float S1 = r1[0], S2 = r2[0];
        float mean = S1 / (float)Ln;
        float var = (S2 - S1 * mean) / (float)(Ln - 1);
        var = fmaxf(var, 0.f);
        float stdp = sqrtf(var) + 1e-5f;
        g_mean[bf] = mean; g_stdp[bf] = stdp; g_istd[bf] = 1.f / stdp;
    }
}

// ---------------- kernel 2: fused K+V projections + KV,Z (512 threads) ----------------
__global__ void __launch_bounds__(512, 2) k_kv(
    const float* __restrict__ x, const float* __restrict__ gamma, const float* __restrict__ beta)
{
    extern __shared__ float sm[];
    float* xns = sm;                     // 64*SR; later phi(K)
    float* vb  = sm + 64 * SR;           // 64*SR
    float* wv  = sm + 2 * 64 * SR;       // 64*WR
    float* wk  = wv + 64 * WR;           // 64*WR
    __shared__ float mus[128], rss[128], As[64], Cs[64];
    __shared__ float dks[64], cks[64], dvs[64], cvs[64];

    int b = blockIdx.y, tid = threadIdx.x;
    int l0b = blockIdx.x * 128;

    if (tid < 64) {
        float a = gamma[tid] * g_istd[b * 64 + tid];
        As[tid] = a;
        Cs[tid] = beta[tid] - g_mean[b * 64 + tid] * a;
        dks[tid] = g_dk[tid]; cks[tid] = g_ck[tid];
        dvs[tid] = g_dv[tid]; cvs[tid] = g_cv[tid];
    }
    // stage weights, padded rows: dst = k*WR + e4 + 4*(e4>=32)
#pragma unroll
    for (int i = 0; i < 2; i++) {
        int idx = tid + i * 512;                  // 1024 float4s
        int kk = idx >> 4, e4 = (idx & 15) * 4;
        int dsto = kk * WR + e4 + ((e4 & 32) >> 3);
        *(float4*)(wv + dsto) = ((const float4*)g_Wvf)[idx];
        *(float4*)(wk + dsto) = ((const float4*)g_Wkf)[idx];
    }
    __syncthreads();
#pragma unroll
    for (int i = 0; i < 4; i++) {
        int idx = tid + i * 512;
        int f = idx >> 5, c = idx & 31;
        float4 v = *(const float4*)(x + ((size_t)(b * 64 + f)) * Ln + l0b + c * 4);
        float a = As[f], c0 = Cs[f];
        v.x = fmaf(v.x, a, c0); v.y = fmaf(v.y, a, c0);
        v.z = fmaf(v.z, a, c0); v.w = fmaf(v.w, a, c0);
        *(float4*)(xns + f * SR + c * 4) = v;
    }
    __syncthreads();
    if (tid < 128) {
        float s1 = 0.f, s2 = 0.f;
#pragma unroll
        for (int f = 0; f < 64; f++) { float t = xns[f * SR + tid]; s1 += t; s2 = fmaf(t, t, s2); }
        float mu = s1 * (1.f / 64.f);
        mus[tid] = mu;
        rss[tid] = rsqrtf(fmaf(-mu, mu, s2 * (1.f / 64.f)) + 1e-5f);
    }
    __syncthreads();

    // thread tile: 2 l x 8 e ; pairs along e (natural in weight memory)
    int lane = tid & 31, wrp = tid >> 5;
    int eg = lane >> 2, lsub = lane & 3;
    int l0 = 2 * (lsub + 4 * wrp);       // 0..126 even
    int e0 = 8 * eg;                     // 0..56
    const float* hp = xns + l0;
    const float* wvp = wv + e0 + ((e0 & 32) >> 3);
    const float* wkp = wk + e0 + ((e0 & 32) >> 3);

    ull aV[4][2], aK[4][2];
#pragma unroll
    for (int i = 0; i < 4; i++) { aV[i][0] = aV[i][1] = aK[i][0] = aK[i][1] = 0ULL; }
#pragma unroll 8
    for (int k = 0; k < 64; k++) {
        float2 hx = *(const float2*)(hp + k * SR);
        ull h0 = dup(hx.x), h1 = dup(hx.y);
        ulonglong2 wvA = *(const ulonglong2*)(wvp + k * WR);
        ulonglong2 wvB = *(const ulonglong2*)(wvp + k * WR + 4);
        ulonglong2 wkA = *(const ulonglong2*)(wkp + k * WR);
        ulonglong2 wkB = *(const ulonglong2*)(wkp + k * WR + 4);
        fma2(aV[0][0], wvA.x, h0); fma2(aV[0][1], wvA.x, h1);
        fma2(aV[1][0], wvA.y, h0); fma2(aV[1][1], wvA.y, h1);
        fma2(aV[2][0], wvB.x, h0); fma2(aV[2][1], wvB.x, h1);
        fma2(aV[3][0], wvB.y, h0); fma2(aV[3][1], wvB.y, h1);
        fma2(aK[0][0], wkA.x, h0); fma2(aK[0][1], wkA.x, h1);
        fma2(aK[1][0], wkA.y, h0); fma2(aK[1][1], wkA.y, h1);
        fma2(aK[2][0], wkB.x, h0); fma2(aK[2][1], wkB.x, h1);
        fma2(aK[3][0], wkB.y, h0); fma2(aK[3][1], wkB.y, h1);
    }

    float mu0 = mus[l0], mu1 = mus[l0 + 1];
    float rs0 = rss[l0], rs1 = rss[l0 + 1];

    // ---- V epilogue -> vb (vb not read by GEMM: no sync needed) ----
#pragma unroll
    for (int ep = 0; ep < 4; ep++) {
        int e = e0 + 2 * ep;
        float2 s0 = upk(aV[ep][0]);   // (v_e, v_{e+1}) at column l0
        float2 s1 = upk(aV[ep][1]);   // at column l0+1
        vb[e * SR + l0]           = fmaf(rs0, s0.x - mu0 * dvs[e],     cvs[e]);
        vb[(e + 1) * SR + l0]     = fmaf(rs0, s0.y - mu0 * dvs[e + 1], cvs[e + 1]);
        vb[e * SR + l0 + 1]       = fmaf(rs1, s1.x - mu1 * dvs[e],     cvs[e]);
        vb[(e + 1) * SR + l0 + 1] = fmaf(rs1, s1.y - mu1 * dvs[e + 1], cvs[e + 1]);
    }
    // ---- K epilogue: phi in regs ----
    float kf[4][4];
#pragma unroll
    for (int ep = 0; ep < 4; ep++) {
        int e = e0 + 2 * ep;
        float2 s0 = upk(aK[ep][0]);
        float2 s1 = upk(aK[ep][1]);
        kf[ep][0] = phi_fn(fmaf(rs0, s0.x - mu0 * dks[e],     cks[e]));
        kf[ep][1] = phi_fn(fmaf(rs0, s0.y - mu0 * dks[e + 1], cks[e + 1]));
        kf[ep][2] = phi_fn(fmaf(rs1, s1.x - mu1 * dks[e],     cks[e]));
        kf[ep][3] = phi_fn(fmaf(rs1, s1.y - mu1 * dks[e + 1], cks[e + 1]));
    }
    __syncthreads();   // all GEMM reads of xns done
#pragma unroll
    for (int ep = 0; ep < 4; ep++) {
        int e = e0 + 2 * ep;
        xns[e * SR + l0]           = kf[ep][0];
        xns[(e + 1) * SR + l0]     = kf[ep][1];
        xns[e * SR + l0 + 1]       = kf[ep][2];
        xns[(e + 1) * SR + l0 + 1] = kf[ep][3];
    }
    __syncthreads();

    // ---- KV accumulation: one (hh,d,e) per thread ----
    {
        int hh = tid >> 6;
        int d  = (tid >> 3) & 7;
        int e2 = tid & 7;
        const float* kr = xns + (hh * 8 + d) * SR;
        const float* vr = vb + (hh * 8 + e2) * SR;
        ull a = 0ULL;
#pragma unroll 8
        for (int j = 0; j < 128; j += 4) {
            ulonglong2 kk = *(const ulonglong2*)(kr + j);
            ulonglong2 vv = *(const ulonglong2*)(vr + j);
            fma2(a, kk.x, vv.x);
            fma2(a, kk.y, vv.y);
        }
        float2 t = upk(a);
        atomicAdd(&g_KV[(b * 8 + hh) * 64 + d * 8 + e2], t.x + t.y);
    }
    if (tid < 64) {
        const float* kr = xns + tid * SR;
        float s = 0.f;
#pragma unroll
        for (int j = 0; j < 128; j += 4) {
            float4 v = *(const float4*)(kr + j);
            s += (v.x + v.y) + (v.z + v.w);
        }
        atomicAdd(&g_Z[b * 64 + tid], s);
    }
}

// ---------------- kernel 3: Q, attention, Wo+residual, fused temporal (512 threads) ----------------
__global__ void __launch_bounds__(512, 2) k_qo(
    const float* __restrict__ x, const float* __restrict__ gamma, const float* __restrict__ beta,
    const float* __restrict__ bo, const float* __restrict__ Wlin)
{
    extern __shared__ float sm[];
    float* wq  = sm;                     // 64*WR (Wq, then WoT)
    float* xns = sm + 64 * WR;           // 64*SR
    float* qb  = sm + 64 * WR + 64 * SR; // 64*SR; later y tile (66-ull row stride)
    ull*   wy  = (ull*)qb;               // y: 64 rows x 66 ulls = 33792 B (region is 64*SR*4 = 33792 exactly)
    ull*   wlu = (ull*)sm;               // Wlin slab: 96 rows x 64 ulls = 49152 B over wq+xns (52224 B)
    __shared__ float mus[128], rss[128], As[64], Cs[64], dqs[64], cqs[64], bos[64];
    __shared__ float KVs[512], Zs[64];

    int b = blockIdx.y, tid = threadIdx.x;
    int l0b = blockIdx.x * 128;

    if (tid < 64) {
        float a = gamma[tid] * g_istd[b * 64 + tid];
        As[tid] = a;
        Cs[tid] = beta[tid] - g_mean[b * 64 + tid] * a;
        dqs[tid] = g_dq[tid]; cqs[tid] = g_cq[tid];
        bos[tid] = bo[tid];
        Zs[tid] = g_Z[b * 64 + tid];
    }
    KVs[tid] = g_KV[b * 512 + tid];
#pragma unroll
    for (int i = 0; i < 2; i++) {
        int idx = tid + i * 512;
        int kk = idx >> 4, e4 = (idx & 15) * 4;
        *(float4*)(wq + kk * WR + e4 + ((e4 & 32) >> 3)) = ((const float4*)g_Wqf)[idx];
    }
    __syncthreads();
#pragma unroll
    for (int i = 0; i < 4; i++) {
        int idx = tid + i * 512;
        int f = idx >> 5, c = idx & 31;
        float4 v = *(const float4*)(x + ((size_t)(b * 64 + f)) * Ln + l0b + c * 4);
        float a = As[f], c0 = Cs[f];
        v.x = fmaf(v.x, a, c0); v.y = fmaf(v.y, a, c0);
        v.z = fmaf(v.z, a, c0); v.w = fmaf(v.w, a, c0);
        *(float4*)(xns + f * SR + c * 4) = v;
    }
    __syncthreads();
    if (tid < 128) {
        float s1 = 0.f, s2 = 0.f;
#pragma unroll
        for (int f = 0; f < 64; f++) { float t = xns[f * SR + tid]; s1 += t; s2 = fmaf(t, t, s2); }
        float mu = s1 * (1.f / 64.f);
        mus[tid] = mu;
        rss[tid] = rsqrtf(fmaf(-mu, mu, s2 * (1.f / 64.f)) + 1e-5f);
    }
    __syncthreads();

    int lane = tid & 31, wrp = tid >> 5;
    int eg = lane >> 2, lsub = lane & 3;
    int l0 = 2 * (lsub + 4 * wrp);
    int e0 = 8 * eg;
    const float* wqp = wq + e0 + ((e0 & 32) >> 3);

    float mu0 = mus[l0], mu1 = mus[l0 + 1];
    float rs0 = rss[l0], rs1 = rss[l0 + 1];

    // ---- Q GEMM -> phi -> qb ----
    {
        const float* hp = xns + l0;
        ull a[4][2];
#pragma unroll
        for (int i = 0; i < 4; i++) { a[i][0] = a[i][1] = 0ULL; }
#pragma unroll 8
        for (int k = 0; k < 64; k++) {
            float2 hx = *(const float2*)(hp + k * SR);
            ull h0 = dup(hx.x), h1 = dup(hx.y);
            ulonglong2 wA = *(const ulonglong2*)(wqp + k * WR);
            ulonglong2 wB = *(const ulonglong2*)(wqp + k * WR + 4);
            fma2(a[0][0], wA.x, h0); fma2(a[0][1], wA.x, h1);
            fma2(a[1][0], wA.y, h0); fma2(a[1][1], wA.y, h1);
            fma2(a[2][0], wB.x, h0); fma2(a[2][1], wB.x, h1);
            fma2(a[3][0], wB.y, h0); fma2(a[3][1], wB.y, h1);
        }
#pragma unroll
        for (int ep = 0; ep < 4; ep++) {
            int e = e0 + 2 * ep;
            float2 s0 = upk(a[ep][0]);
            float2 s1 = upk(a[ep][1]);
            qb[e * SR + l0]           = phi_fn(fmaf(rs0, s0.x - mu0 * dqs[e],     cqs[e]));
            qb[(e + 1) * SR + l0]     = phi_fn(fmaf(rs0, s0.y - mu0 * dqs[e + 1], cqs[e + 1]));
            qb[e * SR + l0 + 1]       = phi_fn(fmaf(rs1, s1.x - mu1 * dqs[e],     cqs[e]));
            qb[(e + 1) * SR + l0 + 1] = phi_fn(fmaf(rs1, s1.y - mu1 * dqs[e + 1], cqs[e + 1]));
        }
    }
    __syncthreads();   // q complete; Wq reads done

    // ---- reload w <- WoT (padded); attention (2 heads/thread, own cells) ----
#pragma unroll
    for (int i = 0; i < 2; i++) {
        int idx = tid + i * 512;
        int kk = idx >> 4, e4 = (idx & 15) * 4;
        *(float4*)(wq + kk * WR + e4 + ((e4 & 32) >> 3)) = ((const float4*)g_Wof)[idx];
    }
    {
        int la = tid & 127;
        int hgrp = tid >> 7;   // 0..3
#pragma unroll
        for (int t = 0; t < 2; t++) {
            int hh = hgrp * 2 + t;
            float q[8];
#pragma unroll
            for (int d = 0; d < 8; d++) q[d] = qb[(hh * 8 + d) * SR + la];
            float nrm = 1e-6f;
#pragma unroll
            for (int d = 0; d < 8; d++) nrm = fmaf(q[d], Zs[hh * 8 + d], nrm);
            float inv = 1.f / nrm;
#pragma unroll
            for (int j = 0; j < 8; j++) {
                float s = 0.f;
#pragma unroll
                for (int d = 0; d < 8; d++) s = fmaf(q[d], KVs[hh * 64 + d * 8 + j], s);
                qb[(hh * 8 + j) * SR + la] = s * inv;
            }
        }
    }
    __syncthreads();

    // ---- Wo GEMM + bias + residual -> y values in regs ----
    float yv[4][4];
    {
        const float* hp = qb + l0;
        ull a[4][2];
#pragma unroll
        for (int i = 0; i < 4; i++) { a[i][0] = a[i][1] = 0ULL; }
#pragma unroll 8
        for (int k = 0; k < 64; k++) {
            float2 hx = *(const float2*)(hp + k * SR);
            ull h0 = dup(hx.x), h1 = dup(hx.y);
            ulonglong2 wA = *(const ulonglong2*)(wqp + k * WR);
            ulonglong2 wB = *(const ulonglong2*)(wqp + k * WR + 4);
            fma2(a[0][0], wA.x, h0); fma2(a[0][1], wA.x, h1);
            fma2(a[1][0], wA.y, h0); fma2(a[1][1], wA.y, h1);
            fma2(a[2][0], wB.x, h0); fma2(a[2][1], wB.x, h1);
            fma2(a[3][0], wB.y, h0); fma2(a[3][1], wB.y, h1);
        }
#pragma unroll
        for (int ep = 0; ep < 4; ep++) {
            int fo = e0 + 2 * ep;
            float2 r0 = *(const float2*)(xns + fo * SR + l0);
            float2 r1 = *(const float2*)(xns + (fo + 1) * SR + l0);
            float2 s0 = upk(a[ep][0]);   // (y_fo, y_fo+1) at l0
            float2 s1 = upk(a[ep][1]);   // at l0+1
            yv[ep][0] = s0.x + bos[fo]     + r0.x;
            yv[ep][1] = s0.y + bos[fo + 1] + r1.x;
            yv[ep][2] = s1.x + bos[fo]     + r0.y;
            yv[ep][3] = s1.y + bos[fo + 1] + r1.y;
        }
    }
    __syncthreads();   // all Wo GEMM qb-reads + residual xns-reads done

    // ---- store y (132-float rows over qb region) + Wlin slab over wq+xns ----
    {
        float* wyf = qb;   // float view, row stride 132
#pragma unroll
        for (int ep = 0; ep < 4; ep++) {
            int fo = e0 + 2 * ep;
            wyf[fo * 132 + l0]           = yv[ep][0];
            wyf[(fo + 1) * 132 + l0]     = yv[ep][1];
            wyf[fo * 132 + l0 + 1]       = yv[ep][2];
            wyf[(fo + 1) * 132 + l0 + 1] = yv[ep][3];
        }
    }
#pragma unroll
    for (int i = 0; i < 6; i++) {
        int idx = tid + i * 512;               // 3072 float4 = 96 rows x 32
        int p = idx >> 5, c4 = idx & 31;
        ((float4*)wlu)[(p << 5) + c4] = *(const float4*)(Wlin + (size_t)p * Ln + l0b + c4 * 4);
    }
    __syncthreads();

    // ---- temporal GEMM: M[b,p,f] += sum_l Wlin[p,l] * y[f,l] ----
    int fg = tid & 15, pg2 = tid >> 4;          // 16 f-groups x 32 p-groups
    ull acc2[3][4];
#pragma unroll
    for (int i = 0; i < 3; i++)
#pragma unroll
        for (int k = 0; k < 4; k++) acc2[i][k] = 0ULL;
#pragma unroll 4
    for (int j = 0; j < 64; j += 2) {
        ulonglong2 yvv[4], wvv[3];
#pragma unroll
        for (int k = 0; k < 4; k++) yvv[k] = *(const ulonglong2*)(wy + (fg + 16 * k) * 66 + j);
#pragma unroll
        for (int i = 0; i < 3; i++) wvv[i] = *(const ulonglong2*)(wlu + (pg2 + 32 * i) * 64 + j);
#pragma unroll
        for (int i = 0; i < 3; i++)
#pragma unroll
            for (int k = 0; k < 4; k++) {
                fma2(acc2[i][k], wvv[i].x, yvv[k].x);
                fma2(acc2[i][k], wvv[i].y, yvv[k].y);
            }
    }
#pragma unroll
    for (int i = 0; i < 3; i++)
#pragma unroll
        for (int k = 0; k < 4; k++) {
            float2 t = upk(acc2[i][k]);
            atomicAdd(&g_M[(b * 96 + pg2 + 32 * i) * 64 + fg + 16 * k], t.x + t.y);
        }
}

// ---------------- kernel 5: denorm + projector ----------------
__global__ void k_epi(const float* __restrict__ gamma, const float* __restrict__ beta,
                      const float* __restrict__ blin, const float* __restrict__ Wp,
                      const float* __restrict__ bp, float* __restrict__ out) {
    int b = blockIdx.x, p = threadIdx.x;
    float bl = blin[p];
    float s = bp[0];
#pragma unroll
    for (int f = 0; f < 64; f++) {
        float y = g_M[(b * 96 + p) * 64 + f] + bl;
        y = (y - beta[f]) / gamma[f];
        y = fmaf(y, g_stdp[b * 64 + f], g_mean[b * 64 + f]);
        s = fmaf(y, Wp[f], s);
    }
    out[b * 96 + p] = s;
}

// ---------------- launch ----------------
extern "C" void kernel_launch(void* const* d_in, const int* in_sizes, int n_in,
                              void* d_out, int out_size) {
    (void)in_sizes; (void)n_in; (void)out_size;
    const float* x     = (const float*)d_in[0];
    const float* gamma = (const float*)d_in[1];
    const float* beta  = (const float*)d_in[2];
    const float* lnw   = (const float*)d_in[3];
    const float* lnb   = (const float*)d_in[4];
    const float* Wq    = (const float*)d_in[5];
    const float* bq    = (const float*)d_in[6];
    const float* Wk    = (const float*)d_in[7];
    const float* bk    = (const float*)d_in[8];
    const float* Wv    = (const float*)d_in[9];
    const float* bv    = (const float*)d_in[10];
    const float* Wo    = (const float*)d_in[11];
    const float* bo    = (const float*)d_in[12];
    const float* Wlin  = (const float*)d_in[13];
    const float* blin  = (const float*)d_in[14];
    const float* Wp    = (const float*)d_in[15];
    const float* bp    = (const float*)d_in[16];
    float* out = (float*)d_out;

    const int SMB_KV = (2 * 64 * SR + 2 * 64 * WR) * 4;   // 67584 + 36864 = 104448 B
    const int SMB_QO = (64 * WR + 2 * 64 * SR) * 4;       // 18432 + 67584 = 86016 B
    cudaFuncSetAttribute(k_kv, cudaFuncAttributeMaxDynamicSharedMemorySize, SMB_KV);
    cudaFuncSetAttribute(k_qo, cudaFuncAttributeMaxDynamicSharedMemorySize, SMB_QO);

    k_prep<<<33, 256>>>(lnw, lnb, Wq, bq, Wk, bk, Wv, bv, Wo);
    k_stats<<<Bn * Fn, 256>>>(x);
    k_kv<<<dim3(Ln / 128, Bn), 512, SMB_KV>>>(x, gamma, beta);
    k_qo<<<dim3(Ln / 128, Bn), 512, SMB_QO>>>(x, gamma, beta, bo, Wlin);
    k_epi<<<Bn, Pn>>>(gamma, beta, blin, Wp, bp, out);
}